// round 3
// baseline (speedup 1.0000x reference)
#include <cuda_runtime.h>
#include <cstdint>

// CRF forward (linear-chain log-partition), B=64, T=2048, K=256.
// Design: 1 cluster (2 CTAs) per batch row. Each CTA owns 128 "next-state" rows j,
// holds E[j,i] = exp(trans[j,i] - rowmax_j) register-resident (64 fp32/thread),
// and per step computes v_j = sum_i E[j,i] * p_i with packed f32x2 FMAs.
// Score vector (256 fp32) exchanged between the two CTAs via DSMEM each step.

#define KSZ 256
#define TSZ 2048
#define NEGV -10000.0f
#define SOSI 2

__device__ __forceinline__ float ex2f(float x) {
    float r; asm("ex2.approx.ftz.f32 %0, %1;" : "=f"(r) : "f"(x)); return r;
}
__device__ __forceinline__ float lg2f_(float x) {
    float r; asm("lg2.approx.ftz.f32 %0, %1;" : "=f"(r) : "f"(x)); return r;
}
__device__ __forceinline__ unsigned long long pack2(float lo, float hi) {
    unsigned long long r; asm("mov.b64 %0, {%1, %2};" : "=l"(r) : "f"(lo), "f"(hi)); return r;
}
__device__ __forceinline__ void unpack2(unsigned long long v, float& lo, float& hi) {
    asm("mov.b64 {%0, %1}, %2;" : "=f"(lo), "=f"(hi) : "l"(v));
}
__device__ __forceinline__ void fma2(unsigned long long& d, unsigned long long a, unsigned long long b) {
    asm("fma.rn.f32x2 %0, %1, %2, %0;" : "+l"(d) : "l"(a), "l"(b));
}
__device__ __forceinline__ uint32_t smem_u32(const void* p) {
    uint32_t a;
    asm("{ .reg .u64 t; cvta.to.shared.u64 t, %1; cvt.u32.u64 %0, t; }" : "=r"(a) : "l"(p));
    return a;
}
__device__ __forceinline__ uint32_t mapa_u32(uint32_t a, uint32_t rk) {
    uint32_t r; asm("mapa.shared::cluster.u32 %0, %1, %2;" : "=r"(r) : "r"(a), "r"(rk)); return r;
}
__device__ __forceinline__ void st_cl(uint32_t a, float v) {
    asm volatile("st.shared::cluster.f32 [%0], %1;" :: "r"(a), "f"(v));
}
__device__ __forceinline__ void cluster_barrier() {
    asm volatile("barrier.cluster.arrive.aligned;" ::: "memory");
    asm volatile("barrier.cluster.wait.aligned;"   ::: "memory");
}

__global__ void __cluster_dims__(2, 1, 1) __launch_bounds__(512, 1)
crf_fwd_kernel(const float* __restrict__ y,
               const float* __restrict__ mask,
               const float* __restrict__ trans,
               float* __restrict__ out)
{
    constexpr float INV_LN2 = 1.4426950408889634f;
    constexpr float LN2F    = 0.6931471805599453f;

    __shared__ float mask_s[TSZ];                    // 8 KB
    __shared__ __align__(16) float p_s[KSZ];         // exp(s - m)
    __shared__ __align__(16) float sbuf[2][KSZ];     // double-buffered scores (full K)
    __shared__ float partial_s[4][128];              // per-i-chunk partial sums
    __shared__ float Mrow_s[128];                    // rowmax of local trans rows
    __shared__ float wmax_s[2][8];                   // per-warp maxima of s (for next m)

    const int tid = threadIdx.x;
    const int w   = tid >> 5;
    const int l   = tid & 31;
    const int jb  = w & 3;        // j-block within CTA (4 blocks of 32)
    const int ic  = w >> 2;       // i-chunk (4 chunks of 64)
    const int jl  = jb * 32 + l;  // local j, 0..127   (== tid for tid<128)
    const int i0  = ic * 64;

    uint32_t rank; asm("mov.u32 %0, %%cluster_ctarank;" : "=r"(rank));
    const uint32_t peer = rank ^ 1u;
    const int b = blockIdx.x >> 1;
    const int jg = (int)rank * 128 + jl;   // global j this thread's E rows belong to

    // ---------------- setup (once) ----------------
    if (tid < 128) {
        const float* row = trans + (size_t)((int)rank * 128 + tid) * KSZ;
        float mx = row[0];
        #pragma unroll 8
        for (int i = 1; i < KSZ; i++) mx = fmaxf(mx, row[i]);
        Mrow_s[tid] = mx;
    }
    for (int i = tid; i < TSZ; i += 512) mask_s[i] = mask[(size_t)b * TSZ + i];
    for (int i = tid; i < KSZ; i += 512) sbuf[0][i] = (i == SOSI) ? 0.0f : NEGV;
    if (tid < 8) wmax_s[0][tid] = 0.0f;   // max(s0) = 0 (the SOS entry)
    __syncthreads();

    // Register-resident E (exp-space transition), 64 values packed as 32 f32x2.
    unsigned long long E2[32];
    {
        const float Mj = Mrow_s[jl];
        const float* row = trans + (size_t)jg * KSZ + i0;
        #pragma unroll
        for (int k = 0; k < 32; k++) {
            float e0 = ex2f((row[2 * k]     - Mj) * INV_LN2);
            float e1 = ex2f((row[2 * k + 1] - Mj) * INV_LN2);
            E2[k] = pack2(e0, e1);
        }
    }

    // Precompute peer DSMEM addresses for the score/wmax slots this thread writes.
    uint32_t pa_s0 = 0, pa_s1 = 0, pa_w0 = 0, pa_w1 = 0;
    if (tid < 128) {
        pa_s0 = mapa_u32(smem_u32(&sbuf[0][(int)rank * 128 + tid]), peer);
        pa_s1 = mapa_u32(smem_u32(&sbuf[1][(int)rank * 128 + tid]), peer);
        if (l == 0) {
            pa_w0 = mapa_u32(smem_u32(&wmax_s[0][(int)rank * 4 + (tid >> 5)]), peer);
            pa_w1 = mapa_u32(smem_u32(&wmax_s[1][(int)rank * 4 + (tid >> 5)]), peer);
        }
    }

    float y_next = 0.0f;
    if (tid < 128) y_next = __ldg(&y[((size_t)b * TSZ) * KSZ + jg]);

    cluster_barrier();   // setup complete on both CTAs

    // ---------------- sequential scan over T ----------------
    for (int t = 0; t < TSZ; t++) {
        const int cb = t & 1, nb = cb ^ 1;

        float m = wmax_s[cb][0];
        #pragma unroll
        for (int k = 1; k < 8; k++) m = fmaxf(m, wmax_s[cb][k]);

        if (tid < KSZ) p_s[tid] = ex2f((sbuf[cb][tid] - m) * INV_LN2);

        const float y_cur = y_next;
        if (tid < 128 && t + 1 < TSZ)
            y_next = __ldg(&y[((size_t)b * TSZ + (t + 1)) * KSZ + jg]);
        __syncthreads();

        // v_j partial over this warp's 64-wide i-chunk: 32 packed FMAs.
        unsigned long long acc0 = pack2(0.0f, 0.0f), acc1 = pack2(0.0f, 0.0f);
        const ulonglong2* pp = reinterpret_cast<const ulonglong2*>(&p_s[i0]);
        #pragma unroll
        for (int q = 0; q < 16; q++) {
            ulonglong2 v = pp[q];           // 4 packed p values (broadcast LDS.128)
            fma2(acc0, E2[2 * q],     v.x);
            fma2(acc1, E2[2 * q + 1], v.y);
        }
        float a0x, a0y, a1x, a1y;
        unpack2(acc0, a0x, a0y);
        unpack2(acc1, a1x, a1y);
        partial_s[ic][jl] = (a0x + a1x) + (a0y + a1y);
        __syncthreads();

        if (tid < 128) {
            float v  = partial_s[0][tid] + partial_s[1][tid] +
                       partial_s[2][tid] + partial_s[3][tid];
            float sn = y_cur + lg2f_(v) * LN2F + Mrow_s[tid] + m;
            float so = sbuf[cb][(int)rank * 128 + tid];
            float sf = (mask_s[t] > 0.5f) ? sn : so;   // exact select (mask is 0/1)
            sbuf[nb][(int)rank * 128 + tid] = sf;
            st_cl(nb ? pa_s1 : pa_s0, sf);             // mirror to peer CTA

            float wm = sf;
            #pragma unroll
            for (int o = 16; o; o >>= 1) wm = fmaxf(wm, __shfl_xor_sync(0xffffffffu, wm, o));
            if (l == 0) {
                wmax_s[nb][(int)rank * 4 + (tid >> 5)] = wm;
                st_cl(nb ? pa_w1 : pa_w0, wm);
            }
        }
        cluster_barrier();   // publishes this step's scores/maxima cluster-wide
    }

    // ---------------- final logsumexp over K ----------------
    if (rank == 0 && tid < 32) {
        const float* sf = sbuf[TSZ & 1];
        float mx = -3.4e38f;
        #pragma unroll
        for (int k = 0; k < 8; k++) mx = fmaxf(mx, sf[tid + 32 * k]);
        #pragma unroll
        for (int o = 16; o; o >>= 1) mx = fmaxf(mx, __shfl_xor_sync(0xffffffffu, mx, o));
        float sum = 0.0f;
        #pragma unroll
        for (int k = 0; k < 8; k++) sum += ex2f((sf[tid + 32 * k] - mx) * INV_LN2);
        #pragma unroll
        for (int o = 16; o; o >>= 1) sum += __shfl_xor_sync(0xffffffffu, sum, o);
        if (tid == 0) out[b] = mx + lg2f_(sum) * LN2F;
    }
}

extern "C" void kernel_launch(void* const* d_in, const int* in_sizes, int n_in,
                              void* d_out, int out_size)
{
    const float* y     = (const float*)d_in[0];   // (B, T, K) f32
    const float* mask  = (const float*)d_in[1];   // (B, T)    f32
    const float* trans = (const float*)d_in[2];   // (K, K)    f32
    float* out = (float*)d_out;                   // (B,)      f32

    const int B = in_sizes[1] / TSZ;              // 64
    crf_fwd_kernel<<<2 * B, 512>>>(y, mask, trans, out);
}

// round 4
// speedup vs baseline: 1.0009x; 1.0009x over previous
#include <cuda_runtime.h>
#include <cstdint>

// CRF forward (linear-chain log-partition), B=64, T=2048, K=256.
// Design: 1 cluster (2 CTAs) per batch row. Each CTA owns 128 "next-state" rows j,
// holds E[j,i] = exp(trans[j,i] - rowmax_j) register-resident (64 fp32/thread),
// and per step computes v_j = sum_i E[j,i] * p_i with packed f32x2 FMAs.
// Score vector (256 fp32) exchanged between the two CTAs via DSMEM each step.

#define KSZ 256
#define TSZ 2048
#define NEGV -10000.0f
#define SOSI 2

__device__ __forceinline__ float ex2f(float x) {
    float r; asm("ex2.approx.ftz.f32 %0, %1;" : "=f"(r) : "f"(x)); return r;
}
__device__ __forceinline__ float lg2f_(float x) {
    float r; asm("lg2.approx.ftz.f32 %0, %1;" : "=f"(r) : "f"(x)); return r;
}
__device__ __forceinline__ unsigned long long pack2(float lo, float hi) {
    unsigned long long r; asm("mov.b64 %0, {%1, %2};" : "=l"(r) : "f"(lo), "f"(hi)); return r;
}
__device__ __forceinline__ void unpack2(unsigned long long v, float& lo, float& hi) {
    asm("mov.b64 {%0, %1}, %2;" : "=f"(lo), "=f"(hi) : "l"(v));
}
__device__ __forceinline__ void fma2(unsigned long long& d, unsigned long long a, unsigned long long b) {
    asm("fma.rn.f32x2 %0, %1, %2, %0;" : "+l"(d) : "l"(a), "l"(b));
}
__device__ __forceinline__ uint32_t smem_u32(const void* p) {
    uint32_t a;
    asm("{ .reg .u64 t; cvta.to.shared.u64 t, %1; cvt.u32.u64 %0, t; }" : "=r"(a) : "l"(p));
    return a;
}
__device__ __forceinline__ uint32_t mapa_u32(uint32_t a, uint32_t rk) {
    uint32_t r; asm("mapa.shared::cluster.u32 %0, %1, %2;" : "=r"(r) : "r"(a), "r"(rk)); return r;
}
__device__ __forceinline__ void st_cl(uint32_t a, float v) {
    asm volatile("st.shared::cluster.f32 [%0], %1;" :: "r"(a), "f"(v));
}
__device__ __forceinline__ void cluster_barrier() {
    asm volatile("barrier.cluster.arrive.aligned;" ::: "memory");
    asm volatile("barrier.cluster.wait.aligned;"   ::: "memory");
}

__global__ void __cluster_dims__(2, 1, 1) __launch_bounds__(512, 1)
crf_fwd_kernel(const float* __restrict__ y,
               const float* __restrict__ mask,
               const float* __restrict__ trans,
               float* __restrict__ out)
{
    constexpr float INV_LN2 = 1.4426950408889634f;
    constexpr float LN2F    = 0.6931471805599453f;

    __shared__ float mask_s[TSZ];                    // 8 KB
    __shared__ __align__(16) float p_s[KSZ];         // exp(s - m)
    __shared__ __align__(16) float sbuf[2][KSZ];     // double-buffered scores (full K)
    __shared__ float partial_s[4][128];              // per-i-chunk partial sums
    __shared__ float Mrow_s[128];                    // rowmax of local trans rows
    __shared__ float wmax_s[2][8];                   // per-warp maxima of s (for next m)

    const int tid = threadIdx.x;
    const int w   = tid >> 5;
    const int l   = tid & 31;
    const int jb  = w & 3;        // j-block within CTA (4 blocks of 32)
    const int ic  = w >> 2;       // i-chunk (4 chunks of 64)
    const int jl  = jb * 32 + l;  // local j, 0..127   (== tid for tid<128)
    const int i0  = ic * 64;

    uint32_t rank; asm("mov.u32 %0, %%cluster_ctarank;" : "=r"(rank));
    const uint32_t peer = rank ^ 1u;
    const int b = blockIdx.x >> 1;
    const int jg = (int)rank * 128 + jl;   // global j this thread's E rows belong to

    // ---------------- setup (once) ----------------
    if (tid < 128) {
        const float* row = trans + (size_t)((int)rank * 128 + tid) * KSZ;
        float mx = row[0];
        #pragma unroll 8
        for (int i = 1; i < KSZ; i++) mx = fmaxf(mx, row[i]);
        Mrow_s[tid] = mx;
    }
    for (int i = tid; i < TSZ; i += 512) mask_s[i] = mask[(size_t)b * TSZ + i];
    for (int i = tid; i < KSZ; i += 512) sbuf[0][i] = (i == SOSI) ? 0.0f : NEGV;
    if (tid < 8) wmax_s[0][tid] = 0.0f;   // max(s0) = 0 (the SOS entry)
    __syncthreads();

    // Register-resident E (exp-space transition), 64 values packed as 32 f32x2.
    unsigned long long E2[32];
    {
        const float Mj = Mrow_s[jl];
        const float* row = trans + (size_t)jg * KSZ + i0;
        #pragma unroll
        for (int k = 0; k < 32; k++) {
            float e0 = ex2f((row[2 * k]     - Mj) * INV_LN2);
            float e1 = ex2f((row[2 * k + 1] - Mj) * INV_LN2);
            E2[k] = pack2(e0, e1);
        }
    }

    // Precompute peer DSMEM addresses for the score/wmax slots this thread writes.
    uint32_t pa_s0 = 0, pa_s1 = 0, pa_w0 = 0, pa_w1 = 0;
    if (tid < 128) {
        pa_s0 = mapa_u32(smem_u32(&sbuf[0][(int)rank * 128 + tid]), peer);
        pa_s1 = mapa_u32(smem_u32(&sbuf[1][(int)rank * 128 + tid]), peer);
        if (l == 0) {
            pa_w0 = mapa_u32(smem_u32(&wmax_s[0][(int)rank * 4 + (tid >> 5)]), peer);
            pa_w1 = mapa_u32(smem_u32(&wmax_s[1][(int)rank * 4 + (tid >> 5)]), peer);
        }
    }

    float y_next = 0.0f;
    if (tid < 128) y_next = __ldg(&y[((size_t)b * TSZ) * KSZ + jg]);

    cluster_barrier();   // setup complete on both CTAs

    // ---------------- sequential scan over T ----------------
    for (int t = 0; t < TSZ; t++) {
        const int cb = t & 1, nb = cb ^ 1;

        float m = wmax_s[cb][0];
        #pragma unroll
        for (int k = 1; k < 8; k++) m = fmaxf(m, wmax_s[cb][k]);

        if (tid < KSZ) p_s[tid] = ex2f((sbuf[cb][tid] - m) * INV_LN2);

        const float y_cur = y_next;
        if (tid < 128 && t + 1 < TSZ)
            y_next = __ldg(&y[((size_t)b * TSZ + (t + 1)) * KSZ + jg]);
        __syncthreads();

        // v_j partial over this warp's 64-wide i-chunk: 32 packed FMAs.
        unsigned long long acc0 = pack2(0.0f, 0.0f), acc1 = pack2(0.0f, 0.0f);
        const ulonglong2* pp = reinterpret_cast<const ulonglong2*>(&p_s[i0]);
        #pragma unroll
        for (int q = 0; q < 16; q++) {
            ulonglong2 v = pp[q];           // 4 packed p values (broadcast LDS.128)
            fma2(acc0, E2[2 * q],     v.x);
            fma2(acc1, E2[2 * q + 1], v.y);
        }
        float a0x, a0y, a1x, a1y;
        unpack2(acc0, a0x, a0y);
        unpack2(acc1, a1x, a1y);
        partial_s[ic][jl] = (a0x + a1x) + (a0y + a1y);
        __syncthreads();

        if (tid < 128) {
            float v  = partial_s[0][tid] + partial_s[1][tid] +
                       partial_s[2][tid] + partial_s[3][tid];
            float sn = y_cur + lg2f_(v) * LN2F + Mrow_s[tid] + m;
            float so = sbuf[cb][(int)rank * 128 + tid];
            float sf = (mask_s[t] > 0.5f) ? sn : so;   // exact select (mask is 0/1)
            sbuf[nb][(int)rank * 128 + tid] = sf;
            st_cl(nb ? pa_s1 : pa_s0, sf);             // mirror to peer CTA

            float wm = sf;
            #pragma unroll
            for (int o = 16; o; o >>= 1) wm = fmaxf(wm, __shfl_xor_sync(0xffffffffu, wm, o));
            if (l == 0) {
                wmax_s[nb][(int)rank * 4 + (tid >> 5)] = wm;
                st_cl(nb ? pa_w1 : pa_w0, wm);
            }
        }
        cluster_barrier();   // publishes this step's scores/maxima cluster-wide
    }

    // ---------------- final logsumexp over K ----------------
    if (rank == 0 && tid < 32) {
        const float* sf = sbuf[TSZ & 1];
        float mx = -3.4e38f;
        #pragma unroll
        for (int k = 0; k < 8; k++) mx = fmaxf(mx, sf[tid + 32 * k]);
        #pragma unroll
        for (int o = 16; o; o >>= 1) mx = fmaxf(mx, __shfl_xor_sync(0xffffffffu, mx, o));
        float sum = 0.0f;
        #pragma unroll
        for (int k = 0; k < 8; k++) sum += ex2f((sf[tid + 32 * k] - mx) * INV_LN2);
        #pragma unroll
        for (int o = 16; o; o >>= 1) sum += __shfl_xor_sync(0xffffffffu, sum, o);
        if (tid == 0) out[b] = mx + lg2f_(sum) * LN2F;
    }
}

extern "C" void kernel_launch(void* const* d_in, const int* in_sizes, int n_in,
                              void* d_out, int out_size)
{
    const float* y     = (const float*)d_in[0];   // (B, T, K) f32
    const float* mask  = (const float*)d_in[1];   // (B, T)    f32
    const float* trans = (const float*)d_in[2];   // (K, K)    f32
    float* out = (float*)d_out;                   // (B,)      f32

    const int B = in_sizes[1] / TSZ;              // 64
    crf_fwd_kernel<<<2 * B, 512>>>(y, mask, trans, out);
}

// round 5
// speedup vs baseline: 1.5473x; 1.5458x over previous
#include <cuda_runtime.h>
#include <cstdint>

// CRF forward (linear-chain log-partition), B=64, T=2048, K=256.
// 1 cluster (2 CTAs) per batch row. E[j,i] = exp(trans[j,i] - rowmax_j) is
// register-resident (64 fp32/thread). Per step each CTA's tail computes its
// 128 new scores AND their exp-space values p, and pushes p to the peer via
// st.async + mbarrier (double-buffered). The softmax shift m is tracked
// lazily: m_{t+1} = m_t + ln(max p_t), reduced by spare warps off the
// critical path. No cluster-wide barrier in the main loop.

#define KSZ 256
#define TSZ 2048
#define NEGV -10000.0f
#define SOSI 2

__device__ __forceinline__ float ex2f(float x) {
    float r; asm("ex2.approx.ftz.f32 %0, %1;" : "=f"(r) : "f"(x)); return r;
}
__device__ __forceinline__ float lg2f_(float x) {
    float r; asm("lg2.approx.ftz.f32 %0, %1;" : "=f"(r) : "f"(x)); return r;
}
__device__ __forceinline__ void unpack2(unsigned long long v, float& lo, float& hi) {
    asm("mov.b64 {%0, %1}, %2;" : "=f"(lo), "=f"(hi) : "l"(v));
}
__device__ __forceinline__ unsigned long long pack2(float lo, float hi) {
    unsigned long long r; asm("mov.b64 %0, {%1, %2};" : "=l"(r) : "f"(lo), "f"(hi)); return r;
}
__device__ __forceinline__ void fma2(unsigned long long& d, unsigned long long a, unsigned long long b) {
    asm("fma.rn.f32x2 %0, %1, %2, %0;" : "+l"(d) : "l"(a), "l"(b));
}
__device__ __forceinline__ uint32_t smem_u32(const void* p) {
    uint32_t a;
    asm("{ .reg .u64 t; cvta.to.shared.u64 t, %1; cvt.u32.u64 %0, t; }" : "=r"(a) : "l"(p));
    return a;
}
__device__ __forceinline__ uint32_t mapa_u32(uint32_t a, uint32_t rk) {
    uint32_t r; asm("mapa.shared::cluster.u32 %0, %1, %2;" : "=r"(r) : "r"(a), "r"(rk)); return r;
}
__device__ __forceinline__ void st_cl(uint32_t a, float v) {
    asm volatile("st.shared::cluster.f32 [%0], %1;" :: "r"(a), "f"(v));
}
// Remote store that also delivers tx-bytes to the peer's mbarrier.
__device__ __forceinline__ void st_async_b32(uint32_t peer_addr, float v, uint32_t peer_bar) {
    asm volatile("st.async.shared::cluster.mbarrier::complete_tx::bytes.b32 [%0], %1, [%2];"
                 :: "r"(peer_addr), "r"(__float_as_uint(v)), "r"(peer_bar) : "memory");
}
__device__ __forceinline__ void mbar_init(uint32_t bar, uint32_t cnt) {
    asm volatile("mbarrier.init.shared.b64 [%0], %1;" :: "r"(bar), "r"(cnt) : "memory");
}
__device__ __forceinline__ void mbar_expect_tx(uint32_t bar, uint32_t bytes) {
    asm volatile("mbarrier.arrive.expect_tx.shared.b64 _, [%0], %1;" :: "r"(bar), "r"(bytes) : "memory");
}
__device__ __forceinline__ void mbar_wait_parity(uint32_t bar, uint32_t par) {
    asm volatile(
        "{\n\t.reg .pred P;\n\t"
        "WL_%=:\n\t"
        "mbarrier.try_wait.parity.acquire.cta.shared::cta.b64 P, [%0], %1, 0x989680;\n\t"
        "@P bra.uni WD_%=;\n\t"
        "bra.uni WL_%=;\n\t"
        "WD_%=:\n\t}"
        :: "r"(bar), "r"(par) : "memory");
}
__device__ __forceinline__ void cluster_barrier() {
    asm volatile("barrier.cluster.arrive.aligned;" ::: "memory");
    asm volatile("barrier.cluster.wait.aligned;"   ::: "memory");
}

__global__ void __cluster_dims__(2, 1, 1) __launch_bounds__(512, 1)
crf_fwd_kernel(const float* __restrict__ y,
               const float* __restrict__ mask,
               const float* __restrict__ trans,
               float* __restrict__ out)
{
    constexpr float INV_LN2 = 1.4426950408889634f;
    constexpr float LN2F    = 0.6931471805599453f;

    __shared__ float mask_s[TSZ];                       // 8 KB
    __shared__ __align__(16) float p_s[2][KSZ];         // double-buffered exp-scores
    __shared__ float partial_s[4][128];                 // per-i-chunk partial sums
    __shared__ float Mrow_s[128];                       // rowmax of local trans rows
    __shared__ float mpart_s[4];                        // per-chunk p-maxima
    __shared__ float sfin_s[128];                       // final scores (own half)
    __shared__ float fin_s[2];                          // peer's (max, sum) at the end
    __shared__ __align__(8) unsigned long long mbar[2]; // double-buffered tx barriers

    const int tid = threadIdx.x;
    const int w   = tid >> 5;
    const int l   = tid & 31;
    const int jb  = w & 3;        // j-block within CTA
    const int ic  = w >> 2;       // i-chunk (4 chunks of 64)
    const int jl  = jb * 32 + l;  // local j, 0..127
    const int i0  = ic * 64;

    uint32_t rank; asm("mov.u32 %0, %%cluster_ctarank;" : "=r"(rank));
    const uint32_t peer = rank ^ 1u;
    const int b  = blockIdx.x >> 1;
    const int jg = (int)rank * 128 + jl;

    // ---------------- setup ----------------
    if (tid == 0) { mbar_init(smem_u32(&mbar[0]), 1); mbar_init(smem_u32(&mbar[1]), 1); }
    if (tid < 128) {
        const float* row = trans + (size_t)((int)rank * 128 + tid) * KSZ;
        float mx = row[0];
        #pragma unroll 8
        for (int i = 1; i < KSZ; i++) mx = fmaxf(mx, row[i]);
        Mrow_s[tid] = mx;
    }
    for (int i = tid; i < TSZ; i += 512) mask_s[i] = mask[(size_t)b * TSZ + i];
    for (int i = tid; i < KSZ; i += 512) p_s[0][i] = (i == SOSI) ? 1.0f : 0.0f; // p0 = exp(s0 - 0)
    __syncthreads();

    // Register-resident E row chunk (64 values as 32 f32x2).
    unsigned long long E2[32];
    {
        const float Mj0 = Mrow_s[jl];
        const float* row = trans + (size_t)jg * KSZ + i0;
        #pragma unroll
        for (int k = 0; k < 32; k++) {
            float e0 = ex2f((row[2 * k]     - Mj0) * INV_LN2);
            float e1 = ex2f((row[2 * k + 1] - Mj0) * INV_LN2);
            E2[k] = pack2(e0, e1);
        }
    }

    // Tail-thread state + peer addresses.
    float Mj = 0.0f, prev_sf = 0.0f, m_run = 0.0f, y_next = 0.0f;
    uint32_t pa_p0 = 0, pa_p1 = 0, pa_b0 = 0, pa_b1 = 0;
    if (tid < 128) {
        Mj      = Mrow_s[tid];
        prev_sf = (jg == SOSI) ? 0.0f : NEGV;
        pa_p0 = mapa_u32(smem_u32(&p_s[0][jg]), peer);
        pa_p1 = mapa_u32(smem_u32(&p_s[1][jg]), peer);
        pa_b0 = mapa_u32(smem_u32(&mbar[0]), peer);
        pa_b1 = mapa_u32(smem_u32(&mbar[1]), peer);
        y_next = __ldg(&y[(size_t)b * TSZ * KSZ + jg]);
    }

    // Which warps touch peer-produced p (i-chunks 0,1 come from rank0's tail,
    // chunks 2,3 from rank1's tail) — only those wait on the mbarrier.
    const bool pmax_warp = (w >= 4) && (w < 8);
    const int  pc = w - 4;
    const bool needs_peer = ((ic >> 1) != (int)rank) ||
                            (pmax_warp && ((pc >> 1) != (int)rank));

    cluster_barrier();   // barriers + smem init visible cluster-wide

    // ---------------- sequential scan over T ----------------
    for (int t = 0; t < TSZ; t++) {
        const int pb = t & 1;
        const float* __restrict__ pcur = p_s[pb];

        if (tid == 0 && t > 0) mbar_expect_tx(smem_u32(&mbar[pb]), 512);

        const float y_cur = y_next;
        if (tid < 128 && t + 1 < TSZ)
            y_next = __ldg(&y[((size_t)b * TSZ + (t + 1)) * KSZ + jg]);

        if (t > 0 && needs_peer) {
            unsigned par = ((unsigned)(t >> 1) + (unsigned)(t & 1) + 1u) & 1u;
            mbar_wait_parity(smem_u32(&mbar[pb]), par);
        }

        // Spare-warp p-max reduce (for the lazy m update), off the tail path.
        if (pmax_warp) {
            float mx = fmaxf(pcur[pc * 64 + l], pcur[pc * 64 + 32 + l]);
            #pragma unroll
            for (int o = 16; o; o >>= 1) mx = fmaxf(mx, __shfl_xor_sync(0xffffffffu, mx, o));
            if (l == 0) mpart_s[pc] = mx;
        }

        // v_j partial over this warp's 64-wide i-chunk: 32 packed FMAs.
        unsigned long long acc0 = 0ull, acc1 = 0ull;
        const ulonglong2* pp = reinterpret_cast<const ulonglong2*>(pcur + i0);
        #pragma unroll
        for (int q = 0; q < 16; q++) {
            ulonglong2 v = pp[q];                 // broadcast LDS.128
            fma2(acc0, E2[2 * q],     v.x);
            fma2(acc1, E2[2 * q + 1], v.y);
        }
        float a0x, a0y, a1x, a1y;
        unpack2(acc0, a0x, a0y);
        unpack2(acc1, a1x, a1y);
        partial_s[ic][jl] = (a0x + a1x) + (a0y + a1y);
        __syncthreads();

        if (tid < 128) {
            float v   = partial_s[0][tid] + partial_s[1][tid] +
                        partial_s[2][tid] + partial_s[3][tid];
            float pmx = fmaxf(fmaxf(mpart_s[0], mpart_s[1]),
                              fmaxf(mpart_s[2], mpart_s[3]));
            float sn  = y_cur + lg2f_(v) * LN2F + Mj + m_run;
            float sf  = (mask_s[t] > 0.5f) ? sn : prev_sf;
            prev_sf   = sf;
            m_run     = m_run + lg2f_(pmx) * LN2F;   // = max(S_t), identical in both CTAs
            if (t + 1 < TSZ) {
                float pv = ex2f((sf - m_run) * INV_LN2);
                p_s[pb ^ 1][jg] = pv;                           // local half
                st_async_b32(pb ? pa_p0 : pa_p1, pv,            // mirror to peer
                             pb ? pa_b0 : pa_b1);
            }
        }
        __syncthreads();   // local p_s[pb^1] half visible before next step
    }

    // ---------------- final logsumexp over K ----------------
    if (tid < 128) sfin_s[tid] = prev_sf;
    __syncthreads();

    float mx = 0.0f, sum = 0.0f;
    if (tid < 32) {
        float a0 = sfin_s[tid], a1 = sfin_s[tid + 32];
        float a2 = sfin_s[tid + 64], a3 = sfin_s[tid + 96];
        mx = fmaxf(fmaxf(a0, a1), fmaxf(a2, a3));
        #pragma unroll
        for (int o = 16; o; o >>= 1) mx = fmaxf(mx, __shfl_xor_sync(0xffffffffu, mx, o));
        sum = ex2f((a0 - mx) * INV_LN2) + ex2f((a1 - mx) * INV_LN2) +
              ex2f((a2 - mx) * INV_LN2) + ex2f((a3 - mx) * INV_LN2);
        #pragma unroll
        for (int o = 16; o; o >>= 1) sum += __shfl_xor_sync(0xffffffffu, sum, o);
        if (tid == 0 && rank == 1) {
            st_cl(mapa_u32(smem_u32(&fin_s[0]), 0u), mx);
            st_cl(mapa_u32(smem_u32(&fin_s[1]), 0u), sum);
        }
    }
    cluster_barrier();
    if (rank == 0 && tid == 0) {
        float mxB = fin_s[0], sumB = fin_s[1];
        float M = fmaxf(mx, mxB);
        float Z = sum  * ex2f((mx  - M) * INV_LN2) +
                  sumB * ex2f((mxB - M) * INV_LN2);
        out[b] = M + lg2f_(Z) * LN2F;
    }
}

extern "C" void kernel_launch(void* const* d_in, const int* in_sizes, int n_in,
                              void* d_out, int out_size)
{
    const float* y     = (const float*)d_in[0];   // (B, T, K) f32
    const float* mask  = (const float*)d_in[1];   // (B, T)    f32
    const float* trans = (const float*)d_in[2];   // (K, K)    f32
    float* out = (float*)d_out;                   // (B,)      f32

    const int B = in_sizes[1] / TSZ;              // 64
    crf_fwd_kernel<<<2 * B, 512>>>(y, mask, trans, out);
}